// round 1
// baseline (speedup 1.0000x reference)
#include <cuda_runtime.h>
#include <cuda_bf16.h>
#include <cstdint>

// Problem constants
#define NPTS     65536        // 64 * 32 * 32 points
#define EDIM     256          // embedding dim (C)
#define NEMB     1024         // number of embeddings (K)
#define PTS_PER_B 1024        // 32*32
#define LAT_B_STRIDE 262144   // 256 * 1024 floats per batch image
#define QUANT_ELEMS 16777216  // 64*256*32*32

// Scratch (no device allocation allowed)
__device__ float  g_eT[EDIM * NEMB];    // transposed embedding [d][k]
__device__ float  g_e2[NEMB];           // |e_k|^2
__device__ float  g_x2[NPTS];           // |x_n|^2
__device__ int    g_bestIdx[NPTS];
__device__ double g_loss_sum;

// ---------------------------------------------------------------------------
__global__ void k_zero() { g_loss_sum = 0.0; }

// 1024 blocks x 256 threads: transpose embedding row k, compute e2[k]
__global__ __launch_bounds__(256) void k_prep(const float* __restrict__ emb) {
    int k = blockIdx.x;
    int c = threadIdx.x;
    float v = emb[k * EDIM + c];
    g_eT[c * NEMB + k] = v;
    __shared__ float s[256];
    s[c] = v * v;
    __syncthreads();
    for (int o = 128; o > 0; o >>= 1) {
        if (c < o) s[c] += s[c + o];
        __syncthreads();
    }
    if (c == 0) g_e2[k] = s[0];
}

// 256 blocks x 256 threads: x2[n] = sum_c lat[b][c][p]^2 (coalesced across p)
__global__ __launch_bounds__(256) void k_x2(const float* __restrict__ lat) {
    int n = blockIdx.x * 256 + threadIdx.x;
    int b = n >> 10;
    int p = n & 1023;
    const float* base = lat + (size_t)b * LAT_B_STRIDE + p;
    float s = 0.f;
#pragma unroll 8
    for (int c = 0; c < EDIM; c++) {
        float a = base[(size_t)c * PTS_PER_B];
        s = fmaf(a, a, s);
    }
    g_x2[n] = s;
}

// ---------------------------------------------------------------------------
// Fused distance GEMM + argmin.
// One CTA = 128 points x all 1024 embeddings (argmin CTA-local).
// Classic 128x128x8 SGEMM tiling, 256 threads, 8x8 per thread.
#define BM 128
#define BN 128
#define BK 8

__global__ __launch_bounds__(256, 2) void k_dist(const float* __restrict__ lat,
                                                 float* __restrict__ out,
                                                 int write_idx) {
    __shared__ float Xs[BK][BM];
    __shared__ float Es[BK][BN];
    __shared__ float sv[BM][16];
    __shared__ int   si[BM][16];

    int tid = threadIdx.x;
    int n_base = blockIdx.x * BM;
    int b = n_base >> 10;
    int p0 = n_base & 1023;
    const float* latb = lat + (size_t)b * LAT_B_STRIDE + p0;

    int rm = tid >> 4;   // 0..15 : point group
    int cn = tid & 15;   // 0..15 : embedding group

    float x2v[8];
#pragma unroll
    for (int i = 0; i < 8; i++) x2v[i] = g_x2[n_base + rm * 8 + i];

    float bestV[8];
    int   bestI[8];
#pragma unroll
    for (int i = 0; i < 8; i++) { bestV[i] = 3.4e38f; bestI[i] = 0; }

    for (int kt = 0; kt < NEMB; kt += BN) {
        float acc[8][8];
#pragma unroll
        for (int i = 0; i < 8; i++)
#pragma unroll
            for (int j = 0; j < 8; j++) acc[i][j] = 0.f;

        for (int d0 = 0; d0 < EDIM; d0 += BK) {
#pragma unroll
            for (int l = 0; l < 4; l++) {
                int e = tid + l * 256;
                int d = e >> 7;
                int m = e & 127;
                Xs[d][m] = latb[(size_t)(d0 + d) * PTS_PER_B + m];
                Es[d][m] = g_eT[(d0 + d) * NEMB + kt + m];
            }
            __syncthreads();
#pragma unroll
            for (int dd = 0; dd < BK; dd++) {
                float a[8], bb[8];
#pragma unroll
                for (int i = 0; i < 8; i++) a[i] = Xs[dd][rm * 8 + i];
#pragma unroll
                for (int j = 0; j < 8; j++) bb[j] = Es[dd][cn * 8 + j];
#pragma unroll
                for (int i = 0; i < 8; i++)
#pragma unroll
                    for (int j = 0; j < 8; j++)
                        acc[i][j] = fmaf(a[i], bb[j], acc[i][j]);
            }
            __syncthreads();
        }

        // epilogue for this K-tile: mimic reference rounding
        //   dist = (x2 + e2) - 2*dot   (strict fp32 rounding, no contraction)
#pragma unroll
        for (int j = 0; j < 8; j++) {
            int k = kt + cn * 8 + j;
            float e2 = g_e2[k];
#pragma unroll
            for (int i = 0; i < 8; i++) {
                float dist = __fsub_rn(__fadd_rn(x2v[i], e2),
                                       __fmul_rn(2.0f, acc[i][j]));
                if (dist < bestV[i]) { bestV[i] = dist; bestI[i] = k; }
            }
        }
    }

    // cross-thread argmin reduction (16 cn-threads share each point)
#pragma unroll
    for (int i = 0; i < 8; i++) {
        sv[rm * 8 + i][cn] = bestV[i];
        si[rm * 8 + i][cn] = bestI[i];
    }
    __syncthreads();
    if (tid < BM) {
        float bv = sv[tid][0];
        int   bi = si[tid][0];
#pragma unroll
        for (int t = 1; t < 16; t++) {
            float v = sv[tid][t];
            int   ii = si[tid][t];
            if (v < bv || (v == bv && ii < bi)) { bv = v; bi = ii; }
        }
        int n = n_base + tid;
        g_bestIdx[n] = bi;
        if (write_idx) out[QUANT_ELEMS + 1 + n] = (float)bi;
    }
}

// ---------------------------------------------------------------------------
// Gather codes -> quant_st output (== quant numerically), accumulate MSE
__global__ __launch_bounds__(256) void k_out(const float* __restrict__ lat,
                                             float* __restrict__ out) {
    int t = threadIdx.x;
    int n = blockIdx.x * 256 + t;
    int b = n >> 10;
    int p = n & 1023;
    size_t base = (size_t)b * LAT_B_STRIDE + p;
    int k = g_bestIdx[n];
    double ds = 0.0;
#pragma unroll 4
    for (int c = 0; c < EDIM; c++) {
        float q = g_eT[c * NEMB + k];
        float x = lat[base + (size_t)c * PTS_PER_B];
        out[base + (size_t)c * PTS_PER_B] = q;
        float d = q - x;
        float sq = d * d;       // squared in fp32 like the reference
        ds += (double)sq;
    }
    __shared__ double s[256];
    s[t] = ds;
    __syncthreads();
    for (int o = 128; o > 0; o >>= 1) {
        if (t < o) s[t] += s[t + o];
        __syncthreads();
    }
    if (t == 0) atomicAdd(&g_loss_sum, s[0]);
}

__global__ void k_fin(float* out) {
    float m = (float)(g_loss_sum * (1.0 / (double)QUANT_ELEMS));
    // loss = q_latent_loss + 0.25 * e_latent_loss, both equal m numerically
    out[QUANT_ELEMS] = __fadd_rn(m, __fmul_rn(0.25f, m));
}

// ---------------------------------------------------------------------------
extern "C" void kernel_launch(void* const* d_in, const int* in_sizes, int n_in,
                              void* d_out, int out_size) {
    const float* lat = (const float*)d_in[0];
    const float* emb = (const float*)d_in[1];
    float* out = (float*)d_out;

    int full = (out_size >= QUANT_ELEMS + 1 + NPTS) ? 1 : 0;

    k_zero<<<1, 1>>>();
    k_prep<<<NEMB, 256>>>(emb);
    k_x2<<<NPTS / 256, 256>>>(lat);
    k_dist<<<NPTS / BM, 256>>>(lat, out, full);
    k_out<<<NPTS / 256, 256>>>(lat, out);
    if (full) k_fin<<<1, 1>>>(out);
}

// round 5
// speedup vs baseline: 1.6941x; 1.6941x over previous
#include <cuda_runtime.h>
#include <cuda_bf16.h>
#include <cstdint>

// ---------------------------------------------------------------- constants
#define NPTS      65536
#define EDIM      256
#define NEMB      1024
#define PTS_PER_B 1024
#define LAT_B_STRIDE 262144
#define QUANT_ELEMS 16777216

// ---------------------------------------------------------------- scratch
__device__ __nv_bfloat16 g_X[NPTS * EDIM];     // bf16(lat) transposed to [n][d]
__device__ __nv_bfloat16 g_E[NEMB * EDIM];     // bf16(embedding) [k][d]
__device__ float  g_eT[EDIM * NEMB];
__device__ float  g_e2[NEMB];
__device__ float  g_x2[NPTS];
__device__ int    g_cand[NPTS * 4];
__device__ int    g_bestIdx[NPTS];
__device__ double g_loss_sum;

// ---------------------------------------------------------------- helpers
__device__ __forceinline__ uint32_t smem_u32(const void* p) {
    uint32_t a;
    asm("{ .reg .u64 t; cvta.to.shared.u64 t, %1; cvt.u32.u64 %0, t; }" : "=r"(a) : "l"(p));
    return a;
}
__device__ __forceinline__ void cpasync16(uint32_t dst, const void* src) {
    asm volatile("cp.async.cg.shared.global [%0], [%1], 16;" :: "r"(dst), "l"(src));
}
#define CP_COMMIT() asm volatile("cp.async.commit_group;" ::: "memory")
#define CP_WAIT(n)  asm volatile("cp.async.wait_group %0;" :: "n"(n) : "memory")

__device__ __forceinline__ void ldm_x4(uint32_t& r0, uint32_t& r1, uint32_t& r2, uint32_t& r3,
                                       uint32_t addr) {
    asm volatile("ldmatrix.sync.aligned.m8n8.x4.shared.b16 {%0,%1,%2,%3}, [%4];"
        : "=r"(r0), "=r"(r1), "=r"(r2), "=r"(r3) : "r"(addr));
}
__device__ __forceinline__ void mma_bf16(float& c0, float& c1, float& c2, float& c3,
                                         uint32_t a0, uint32_t a1, uint32_t a2, uint32_t a3,
                                         uint32_t b0, uint32_t b1) {
    asm volatile("mma.sync.aligned.m16n8k16.row.col.f32.bf16.bf16.f32 "
        "{%0,%1,%2,%3}, {%4,%5,%6,%7}, {%8,%9}, {%0,%1,%2,%3};"
        : "+f"(c0), "+f"(c1), "+f"(c2), "+f"(c3)
        : "r"(a0), "r"(a1), "r"(a2), "r"(a3), "r"(b0), "r"(b1));
}

// ---------------------------------------------------------------- small kernels
__global__ void k_zero() { g_loss_sum = 0.0; }

__global__ __launch_bounds__(256) void k_prep(const float* __restrict__ emb) {
    int k = blockIdx.x, c = threadIdx.x;
    float v = emb[k * EDIM + c];
    g_eT[c * NEMB + k] = v;
    g_E[k * EDIM + c] = __float2bfloat16(v);
    __shared__ float s[256];
    s[c] = v * v;
    __syncthreads();
    for (int o = 128; o > 0; o >>= 1) { if (c < o) s[c] += s[c + o]; __syncthreads(); }
    if (c == 0) g_e2[k] = s[0];
}

// transpose [b][c][p] -> X[n][d] bf16; block = 32 points
__global__ __launch_bounds__(256) void k_convX(const float* __restrict__ lat) {
    __shared__ unsigned short sh[8][40];
    int n0 = blockIdx.x * 32;
    int b = n0 >> 10, p0 = n0 & 1023;
    int t = threadIdx.x, ty = t >> 5, tx = t & 31;
    const float* base = lat + (size_t)b * LAT_B_STRIDE + p0;
    for (int d0 = 0; d0 < EDIM; d0 += 8) {
        float v = base[(size_t)(d0 + ty) * PTS_PER_B + tx];
        sh[ty][tx] = __bfloat16_as_ushort(__float2bfloat16(v));
        __syncthreads();
        if (t < 32) {
            uint4 u;
            u.x = (uint32_t)sh[0][t] | ((uint32_t)sh[1][t] << 16);
            u.y = (uint32_t)sh[2][t] | ((uint32_t)sh[3][t] << 16);
            u.z = (uint32_t)sh[4][t] | ((uint32_t)sh[5][t] << 16);
            u.w = (uint32_t)sh[6][t] | ((uint32_t)sh[7][t] << 16);
            *(uint4*)(g_X + (size_t)(n0 + t) * EDIM + d0) = u;
        }
        __syncthreads();
    }
}

__global__ __launch_bounds__(256) void k_x2(const float* __restrict__ lat) {
    int n = blockIdx.x * 256 + threadIdx.x;
    int b = n >> 10, p = n & 1023;
    const float* base = lat + (size_t)b * LAT_B_STRIDE + p;
    float s = 0.f;
#pragma unroll 8
    for (int c = 0; c < EDIM; c++) { float a = base[(size_t)c * PTS_PER_B]; s = fmaf(a, a, s); }
    g_x2[n] = s;
}

// ---------------------------------------------------------------- fused bf16 HMMA distance + top-4
// smem: Xs [128][264] bf16 (67584 B), Es 2 x [128][264] bf16, e2s 2 x 128 f32
#define PADH 264
#define ROWB 528                 // PADH * 2 bytes
#define XSZ  67584               // 128 * 528
#define ESZ  67584
#define SM_ES   XSZ
#define SM_E2   (XSZ + 2 * ESZ)          // 202752
#define SMEM_P1 (SM_E2 + 1024)           // 203776 bytes

__global__ __launch_bounds__(256, 1) void k_dist_tc() {
    extern __shared__ char smem[];
    uint32_t sb = smem_u32(smem);
    int tid = threadIdx.x;
    int wid = tid >> 5, l = tid & 31;
    int warp_m = wid >> 1, warp_n = wid & 1;
    int gid = l >> 2, tig = l & 3;
    int n_base = blockIdx.x * 128;

    // ---- issue X tile + chunk0 loads (group 0)
    for (int i = tid; i < 4096; i += 256) {
        int row = i >> 5, v = i & 31;
        cpasync16(sb + row * ROWB + v * 16, g_X + (size_t)(n_base + row) * EDIM + v * 8);
    }
    for (int i = tid; i < 4096; i += 256) {
        int row = i >> 5, v = i & 31;
        cpasync16(sb + SM_ES + row * ROWB + v * 16, g_E + (size_t)row * EDIM + v * 8);
    }
    if (tid < 32) cpasync16(sb + SM_E2 + tid * 16, g_e2 + tid * 4);
    CP_COMMIT();

    // ldmatrix address offsets (bytes, within tile)
    uint32_t a_off[2], b_off[4];
#pragma unroll
    for (int mt = 0; mt < 2; mt++)
        a_off[mt] = (uint32_t)((warp_m * 32 + mt * 16 + (l & 15)) * ROWB + ((l >> 4) & 1) * 16);
#pragma unroll
    for (int jj = 0; jj < 4; jj++)
        b_off[jj] = (uint32_t)((warp_n * 64 + jj * 16 + ((l >> 4) & 1) * 8 + (l & 7)) * ROWB
                               + ((l >> 3) & 1) * 16);

    float bd[4][4]; int bi[4][4];
#pragma unroll
    for (int g = 0; g < 4; g++)
#pragma unroll
        for (int q = 0; q < 4; q++) { bd[g][q] = 3.4e38f; bi[g][q] = 0; }

    for (int c = 0; c < 8; c++) {
        int buf = c & 1;
        if (c < 7) {
            int nb = (c + 1) & 1;
            for (int i = tid; i < 4096; i += 256) {
                int row = i >> 5, v = i & 31;
                cpasync16(sb + SM_ES + nb * ESZ + row * ROWB + v * 16,
                          g_E + (size_t)((c + 1) * 128 + row) * EDIM + v * 8);
            }
            if (tid < 32) cpasync16(sb + SM_E2 + nb * 512 + tid * 16, g_e2 + (c + 1) * 128 + tid * 4);
            CP_COMMIT();
            CP_WAIT(1);
        } else {
            CP_WAIT(0);
        }
        __syncthreads();

        float acc[2][8][4];
#pragma unroll
        for (int mt = 0; mt < 2; mt++)
#pragma unroll
            for (int jt = 0; jt < 8; jt++)
#pragma unroll
                for (int q = 0; q < 4; q++) acc[mt][jt][q] = 0.f;

        uint32_t eb = sb + SM_ES + buf * ESZ;
#pragma unroll 4
        for (int kc = 0; kc < 16; kc++) {
            uint32_t a[2][4], br[4][4];
#pragma unroll
            for (int mt = 0; mt < 2; mt++)
                ldm_x4(a[mt][0], a[mt][1], a[mt][2], a[mt][3], sb + a_off[mt] + kc * 32);
#pragma unroll
            for (int jj = 0; jj < 4; jj++)
                ldm_x4(br[jj][0], br[jj][1], br[jj][2], br[jj][3], eb + b_off[jj] + kc * 32);
#pragma unroll
            for (int mt = 0; mt < 2; mt++)
#pragma unroll
                for (int jt = 0; jt < 8; jt++)
                    mma_bf16(acc[mt][jt][0], acc[mt][jt][1], acc[mt][jt][2], acc[mt][jt][3],
                             a[mt][0], a[mt][1], a[mt][2], a[mt][3],
                             br[jt >> 1][(jt & 1) * 2], br[jt >> 1][(jt & 1) * 2 + 1]);
        }

        // epilogue: rank by s = e2 - 2*dot (x2 is per-point constant)
        int nck = c * 128 + warp_n * 64;
        const float2* e2p = (const float2*)(smem + SM_E2 + buf * 512 + warp_n * 256);
#pragma unroll
        for (int jt = 0; jt < 8; jt++) {
            float2 e2v = e2p[jt * 4 + tig];
            int nb0 = nck + jt * 8 + tig * 2;
#pragma unroll
            for (int mt = 0; mt < 2; mt++)
#pragma unroll
                for (int s = 0; s < 2; s++) {
                    int g = mt * 2 + s;
                    float d0 = fmaf(-2.f, acc[mt][jt][s * 2 + 0], e2v.x);
                    float d1 = fmaf(-2.f, acc[mt][jt][s * 2 + 1], e2v.y);
                    if (d0 < bd[g][3]) {
                        float dv = d0; int iv = nb0;
#pragma unroll
                        for (int q = 0; q < 4; q++)
                            if (dv < bd[g][q]) {
                                float tf = bd[g][q]; int ti = bi[g][q];
                                bd[g][q] = dv; bi[g][q] = iv; dv = tf; iv = ti;
                            }
                    }
                    if (d1 < bd[g][3]) {
                        float dv = d1; int iv = nb0 + 1;
#pragma unroll
                        for (int q = 0; q < 4; q++)
                            if (dv < bd[g][q]) {
                                float tf = bd[g][q]; int ti = bi[g][q];
                                bd[g][q] = dv; bi[g][q] = iv; dv = tf; iv = ti;
                            }
                    }
                }
        }
        __syncthreads();   // protect Es buffer before next prefetch overwrites
    }

    // ---- merge per-row top-4 across the 8 contributing threads (reuse Es smem)
    float* sd = (float*)(smem + SM_ES);
    int*   si = (int*)(smem + SM_ES + 16384);
    int slot = warp_n * 4 + tig;
#pragma unroll
    for (int mt = 0; mt < 2; mt++)
#pragma unroll
        for (int s = 0; s < 2; s++) {
            int g = mt * 2 + s;
            int row = warp_m * 32 + mt * 16 + s * 8 + gid;
#pragma unroll
            for (int q = 0; q < 4; q++) {
                sd[row * 32 + slot * 4 + q] = bd[g][q];
                si[row * 32 + slot * 4 + q] = bi[g][q];
            }
        }
    __syncthreads();
    if (tid < 128) {
        float fb[4]; int fi[4];
#pragma unroll
        for (int q = 0; q < 4; q++) { fb[q] = 3.4e38f; fi[q] = 0; }
        for (int e = 0; e < 32; e++) {
            float dv = sd[tid * 32 + e]; int iv = si[tid * 32 + e];
            if (dv < fb[3]) {
#pragma unroll
                for (int q = 0; q < 4; q++)
                    if (dv < fb[q]) {
                        float tf = fb[q]; int ti = fi[q];
                        fb[q] = dv; fi[q] = iv; dv = tf; iv = ti;
                    }
            }
        }
#pragma unroll
        for (int q = 0; q < 4; q++) g_cand[(n_base + tid) * 4 + q] = fi[q];
    }
}

// ---------------------------------------------------------------- exact fp32 re-rank + loss
__global__ __launch_bounds__(256) void k_rerank(const float* __restrict__ lat,
                                                const float* __restrict__ emb,
                                                float* __restrict__ out, int full) {
    int t = threadIdx.x;
    int n = blockIdx.x * 256 + t;
    int b = n >> 10, p = n & 1023;
    const float* lp = lat + (size_t)b * LAT_B_STRIDE + p;
    int c0 = g_cand[n * 4 + 0], c1 = g_cand[n * 4 + 1];
    int c2 = g_cand[n * 4 + 2], c3 = g_cand[n * 4 + 3];
    const float* e0 = emb + (size_t)c0 * EDIM;
    const float* e1 = emb + (size_t)c1 * EDIM;
    const float* e2p = emb + (size_t)c2 * EDIM;
    const float* e3 = emb + (size_t)c3 * EDIM;
    float d0 = 0.f, d1 = 0.f, d2 = 0.f, d3 = 0.f;
#pragma unroll 4
    for (int d = 0; d < EDIM; d++) {
        float x = lp[(size_t)d * PTS_PER_B];
        d0 = fmaf(x, e0[d], d0);
        d1 = fmaf(x, e1[d], d1);
        d2 = fmaf(x, e2p[d], d2);
        d3 = fmaf(x, e3[d], d3);
    }
    float x2 = g_x2[n];
    float best = 3.4e38f; int bk = 0x7fffffff;
    float dd; int kk;
    dd = __fsub_rn(__fadd_rn(x2, g_e2[c0]), __fmul_rn(2.f, d0)); kk = c0;
    if (dd < best || (dd == best && kk < bk)) { best = dd; bk = kk; }
    dd = __fsub_rn(__fadd_rn(x2, g_e2[c1]), __fmul_rn(2.f, d1)); kk = c1;
    if (dd < best || (dd == best && kk < bk)) { best = dd; bk = kk; }
    dd = __fsub_rn(__fadd_rn(x2, g_e2[c2]), __fmul_rn(2.f, d2)); kk = c2;
    if (dd < best || (dd == best && kk < bk)) { best = dd; bk = kk; }
    dd = __fsub_rn(__fadd_rn(x2, g_e2[c3]), __fmul_rn(2.f, d3)); kk = c3;
    if (dd < best || (dd == best && kk < bk)) { best = dd; bk = kk; }
    g_bestIdx[n] = bk;
    if (full) out[QUANT_ELEMS + 1 + n] = (float)bk;

    // loss: sum_d (q-x)^2 == best squared distance (exact same magnitude class)
    __shared__ double s[256];
    s[t] = (double)best;
    __syncthreads();
    for (int o = 128; o > 0; o >>= 1) { if (t < o) s[t] += s[t + o]; __syncthreads(); }
    if (t == 0) atomicAdd(&g_loss_sum, s[0]);
}

// ---------------------------------------------------------------- gather write
__global__ __launch_bounds__(256) void k_out(float* __restrict__ out) {
    int n = blockIdx.x * 256 + threadIdx.x;
    int b = n >> 10, p = n & 1023;
    size_t base = (size_t)b * LAT_B_STRIDE + p;
    int k = g_bestIdx[n];
#pragma unroll 4
    for (int c = 0; c < EDIM; c++)
        out[base + (size_t)c * PTS_PER_B] = g_eT[c * NEMB + k];
}

__global__ void k_fin(float* out) {
    float m = (float)(g_loss_sum * (1.0 / (double)QUANT_ELEMS));
    out[QUANT_ELEMS] = __fadd_rn(m, __fmul_rn(0.25f, m));
}

// ---------------------------------------------------------------- launch
extern "C" void kernel_launch(void* const* d_in, const int* in_sizes, int n_in,
                              void* d_out, int out_size) {
    const float* lat = (const float*)d_in[0];
    const float* emb = (const float*)d_in[1];
    float* out = (float*)d_out;
    int full = (out_size >= QUANT_ELEMS + 1 + NPTS) ? 1 : 0;

    cudaFuncSetAttribute(k_dist_tc, cudaFuncAttributeMaxDynamicSharedMemorySize, SMEM_P1);

    k_zero<<<1, 1>>>();
    k_prep<<<NEMB, 256>>>(emb);
    k_convX<<<NPTS / 32, 256>>>(lat);
    k_x2<<<NPTS / 256, 256>>>(lat);
    k_dist_tc<<<NPTS / 128, 256, SMEM_P1>>>();
    k_rerank<<<NPTS / 256, 256>>>(lat, emb, out, full);
    k_out<<<NPTS / 256, 256>>>(out);
    if (full) k_fin<<<1, 1>>>(out);
}

// round 7
// speedup vs baseline: 1.7453x; 1.0302x over previous
#include <cuda_runtime.h>
#include <cuda_bf16.h>
#include <cstdint>

// ---------------------------------------------------------------- constants
#define NPTS      65536
#define EDIM      256
#define NEMB      1024
#define PTS_PER_B 1024
#define LAT_B_STRIDE 262144
#define QUANT_ELEMS 16777216

// ---------------------------------------------------------------- scratch
__device__ __nv_bfloat16 g_X[NPTS * EDIM];     // bf16(lat) transposed to [n][d]
__device__ __nv_bfloat16 g_E[NEMB * EDIM];     // bf16(embedding) [k][d]
__device__ float  g_eT[EDIM * NEMB];
__device__ float  g_e2[NEMB];
__device__ float  g_x2[NPTS];
__device__ int    g_cand[NPTS * 4];
__device__ double g_loss_sum;

// ---------------------------------------------------------------- helpers
__device__ __forceinline__ uint32_t smem_u32(const void* p) {
    uint32_t a;
    asm("{ .reg .u64 t; cvta.to.shared.u64 t, %1; cvt.u32.u64 %0, t; }" : "=r"(a) : "l"(p));
    return a;
}
__device__ __forceinline__ void cpasync16(uint32_t dst, const void* src) {
    asm volatile("cp.async.cg.shared.global [%0], [%1], 16;" :: "r"(dst), "l"(src));
}
#define CP_COMMIT() asm volatile("cp.async.commit_group;" ::: "memory")
#define CP_WAIT(n)  asm volatile("cp.async.wait_group %0;" :: "n"(n) : "memory")

__device__ __forceinline__ void ldm_x4(uint32_t& r0, uint32_t& r1, uint32_t& r2, uint32_t& r3,
                                       uint32_t addr) {
    asm volatile("ldmatrix.sync.aligned.m8n8.x4.shared.b16 {%0,%1,%2,%3}, [%4];"
        : "=r"(r0), "=r"(r1), "=r"(r2), "=r"(r3) : "r"(addr));
}
__device__ __forceinline__ void mma_bf16(float& c0, float& c1, float& c2, float& c3,
                                         uint32_t a0, uint32_t a1, uint32_t a2, uint32_t a3,
                                         uint32_t b0, uint32_t b1) {
    asm volatile("mma.sync.aligned.m16n8k16.row.col.f32.bf16.bf16.f32 "
        "{%0,%1,%2,%3}, {%4,%5,%6,%7}, {%8,%9}, {%0,%1,%2,%3};"
        : "+f"(c0), "+f"(c1), "+f"(c2), "+f"(c3)
        : "r"(a0), "r"(a1), "r"(a2), "r"(a3), "r"(b0), "r"(b1));
}

// ---------------------------------------------------------------- small kernels
__global__ void k_zero() { g_loss_sum = 0.0; }

__global__ __launch_bounds__(256) void k_prep(const float* __restrict__ emb) {
    int k = blockIdx.x, c = threadIdx.x;
    float v = emb[k * EDIM + c];
    g_eT[c * NEMB + k] = v;
    g_E[k * EDIM + c] = __float2bfloat16(v);
    __shared__ float s[256];
    s[c] = v * v;
    __syncthreads();
    for (int o = 128; o > 0; o >>= 1) { if (c < o) s[c] += s[c + o]; __syncthreads(); }
    if (c == 0) g_e2[k] = s[0];
}

// ---------------------------------------------------------------- fused transpose+bf16-convert+x2
// block = 64 points x 256 dims. smem float sF[256][66].
#define CPAD 66
#define CONV_SMEM (256 * CPAD * 4)   // 67584 bytes

__global__ __launch_bounds__(256, 3) void k_convX2(const float* __restrict__ lat) {
    extern __shared__ float sF[];    // [256][CPAD], d-major
    int n0 = blockIdx.x * 64;
    int b = n0 >> 10, p0 = n0 & 1023;
    int t = threadIdx.x;
    int w = t >> 5, l = t & 31;
    const float* base = lat + (size_t)b * LAT_B_STRIDE + p0;

    // load: warp w covers d-rows [w*32, w*32+32); two rows per step, 16 lanes x float4
    int half = l >> 4;           // 0/1 : which of the two rows
    int pf = l & 15;             // float4 index within row
#pragma unroll
    for (int r = 0; r < 16; r++) {
        int d = w * 32 + r * 2 + half;
        float4 v = *(const float4*)(base + (size_t)d * PTS_PER_B + pf * 4);
        float* dst = sF + d * CPAD + pf * 4;
        dst[0] = v.x; dst[1] = v.y; dst[2] = v.z; dst[3] = v.w;
    }
    __syncthreads();

    // output: 4 threads per point; thread covers 64 dims; also x2 partial
    int p = t >> 2, seg = t & 3;
    float s = 0.f;
    uint32_t pk[32];
#pragma unroll
    for (int j = 0; j < 32; j++) {
        float a = sF[(seg * 64 + 2 * j) * CPAD + p];
        float c = sF[(seg * 64 + 2 * j + 1) * CPAD + p];
        s = fmaf(a, a, s);
        s = fmaf(c, c, s);
        unsigned short lo = __bfloat16_as_ushort(__float2bfloat16(a));
        unsigned short hi = __bfloat16_as_ushort(__float2bfloat16(c));
        pk[j] = (uint32_t)lo | ((uint32_t)hi << 16);
    }
    // write 128B (8 x uint4)
    uint4* dst = (uint4*)(g_X + (size_t)(n0 + p) * EDIM + seg * 64);
#pragma unroll
    for (int j = 0; j < 8; j++)
        dst[j] = make_uint4(pk[j * 4], pk[j * 4 + 1], pk[j * 4 + 2], pk[j * 4 + 3]);
    // deterministic pairwise combine of the 4 seg partials
    s += __shfl_xor_sync(0xffffffffu, s, 1);
    s += __shfl_xor_sync(0xffffffffu, s, 2);
    if (seg == 0) g_x2[n0 + p] = s;
}

// ---------------------------------------------------------------- fused bf16 HMMA distance + top-4
#define PADH 264
#define ROWB 528
#define XSZ  67584
#define ESZ  67584
#define SM_ES   XSZ
#define SM_E2   (XSZ + 2 * ESZ)
#define SMEM_P1 (SM_E2 + 1024)

__global__ __launch_bounds__(256, 1) void k_dist_tc() {
    extern __shared__ char smem[];
    uint32_t sb = smem_u32(smem);
    int tid = threadIdx.x;
    int wid = tid >> 5, l = tid & 31;
    int warp_m = wid >> 1, warp_n = wid & 1;
    int gid = l >> 2, tig = l & 3;
    int n_base = blockIdx.x * 128;

    for (int i = tid; i < 4096; i += 256) {
        int row = i >> 5, v = i & 31;
        cpasync16(sb + row * ROWB + v * 16, g_X + (size_t)(n_base + row) * EDIM + v * 8);
    }
    for (int i = tid; i < 4096; i += 256) {
        int row = i >> 5, v = i & 31;
        cpasync16(sb + SM_ES + row * ROWB + v * 16, g_E + (size_t)row * EDIM + v * 8);
    }
    if (tid < 32) cpasync16(sb + SM_E2 + tid * 16, g_e2 + tid * 4);
    CP_COMMIT();

    uint32_t a_off[2], b_off[4];
#pragma unroll
    for (int mt = 0; mt < 2; mt++)
        a_off[mt] = (uint32_t)((warp_m * 32 + mt * 16 + (l & 15)) * ROWB + ((l >> 4) & 1) * 16);
#pragma unroll
    for (int jj = 0; jj < 4; jj++)
        b_off[jj] = (uint32_t)((warp_n * 64 + jj * 16 + ((l >> 4) & 1) * 8 + (l & 7)) * ROWB
                               + ((l >> 3) & 1) * 16);

    float bd[4][4]; int bi[4][4];
#pragma unroll
    for (int g = 0; g < 4; g++)
#pragma unroll
        for (int q = 0; q < 4; q++) { bd[g][q] = 3.4e38f; bi[g][q] = 0; }

    for (int c = 0; c < 8; c++) {
        int buf = c & 1;
        if (c < 7) {
            int nb = (c + 1) & 1;
            for (int i = tid; i < 4096; i += 256) {
                int row = i >> 5, v = i & 31;
                cpasync16(sb + SM_ES + nb * ESZ + row * ROWB + v * 16,
                          g_E + (size_t)((c + 1) * 128 + row) * EDIM + v * 8);
            }
            if (tid < 32) cpasync16(sb + SM_E2 + nb * 512 + tid * 16, g_e2 + (c + 1) * 128 + tid * 4);
            CP_COMMIT();
            CP_WAIT(1);
        } else {
            CP_WAIT(0);
        }
        __syncthreads();

        float acc[2][8][4];
#pragma unroll
        for (int mt = 0; mt < 2; mt++)
#pragma unroll
            for (int jt = 0; jt < 8; jt++)
#pragma unroll
                for (int q = 0; q < 4; q++) acc[mt][jt][q] = 0.f;

        uint32_t eb = sb + SM_ES + buf * ESZ;
#pragma unroll 4
        for (int kc = 0; kc < 16; kc++) {
            uint32_t a[2][4], br[4][4];
#pragma unroll
            for (int mt = 0; mt < 2; mt++)
                ldm_x4(a[mt][0], a[mt][1], a[mt][2], a[mt][3], sb + a_off[mt] + kc * 32);
#pragma unroll
            for (int jj = 0; jj < 4; jj++)
                ldm_x4(br[jj][0], br[jj][1], br[jj][2], br[jj][3], eb + b_off[jj] + kc * 32);
#pragma unroll
            for (int mt = 0; mt < 2; mt++)
#pragma unroll
                for (int jt = 0; jt < 8; jt++)
                    mma_bf16(acc[mt][jt][0], acc[mt][jt][1], acc[mt][jt][2], acc[mt][jt][3],
                             a[mt][0], a[mt][1], a[mt][2], a[mt][3],
                             br[jt >> 1][(jt & 1) * 2], br[jt >> 1][(jt & 1) * 2 + 1]);
        }

        int nck = c * 128 + warp_n * 64;
        const float2* e2p = (const float2*)(smem + SM_E2 + buf * 512 + warp_n * 256);
#pragma unroll
        for (int jt = 0; jt < 8; jt++) {
            float2 e2v = e2p[jt * 4 + tig];
            int nb0 = nck + jt * 8 + tig * 2;
#pragma unroll
            for (int mt = 0; mt < 2; mt++)
#pragma unroll
                for (int s = 0; s < 2; s++) {
                    int g = mt * 2 + s;
                    float d0 = fmaf(-2.f, acc[mt][jt][s * 2 + 0], e2v.x);
                    float d1 = fmaf(-2.f, acc[mt][jt][s * 2 + 1], e2v.y);
                    if (d0 < bd[g][3]) {
                        float dv = d0; int iv = nb0;
#pragma unroll
                        for (int q = 0; q < 4; q++)
                            if (dv < bd[g][q]) {
                                float tf = bd[g][q]; int ti = bi[g][q];
                                bd[g][q] = dv; bi[g][q] = iv; dv = tf; iv = ti;
                            }
                    }
                    if (d1 < bd[g][3]) {
                        float dv = d1; int iv = nb0 + 1;
#pragma unroll
                        for (int q = 0; q < 4; q++)
                            if (dv < bd[g][q]) {
                                float tf = bd[g][q]; int ti = bi[g][q];
                                bd[g][q] = dv; bi[g][q] = iv; dv = tf; iv = ti;
                            }
                    }
                }
        }
        __syncthreads();
    }

    float* sd = (float*)(smem + SM_ES);
    int*   si = (int*)(smem + SM_ES + 16384);
    int slot = warp_n * 4 + tig;
#pragma unroll
    for (int mt = 0; mt < 2; mt++)
#pragma unroll
        for (int s = 0; s < 2; s++) {
            int g = mt * 2 + s;
            int row = warp_m * 32 + mt * 16 + s * 8 + gid;
#pragma unroll
            for (int q = 0; q < 4; q++) {
                sd[row * 32 + slot * 4 + q] = bd[g][q];
                si[row * 32 + slot * 4 + q] = bi[g][q];
            }
        }
    __syncthreads();
    if (tid < 128) {
        float fb[4]; int fi[4];
#pragma unroll
        for (int q = 0; q < 4; q++) { fb[q] = 3.4e38f; fi[q] = 0; }
        for (int e = 0; e < 32; e++) {
            float dv = sd[tid * 32 + e]; int iv = si[tid * 32 + e];
            if (dv < fb[3]) {
#pragma unroll
                for (int q = 0; q < 4; q++)
                    if (dv < fb[q]) {
                        float tf = fb[q]; int ti = fi[q];
                        fb[q] = dv; fi[q] = iv; dv = tf; iv = ti;
                    }
            }
        }
#pragma unroll
        for (int q = 0; q < 4; q++) g_cand[(n_base + tid) * 4 + q] = fi[q];
    }
}

// ---------------------------------------------------------------- fused exact re-rank + loss + gather-write
__global__ __launch_bounds__(256) void k_rerank_out(const float* __restrict__ lat,
                                                    const float* __restrict__ emb,
                                                    float* __restrict__ out, int full) {
    int t = threadIdx.x;
    int n = blockIdx.x * 256 + t;
    int b = n >> 10, p = n & 1023;
    size_t base = (size_t)b * LAT_B_STRIDE + p;
    const float* lp = lat + base;
    int c0 = g_cand[n * 4 + 0], c1 = g_cand[n * 4 + 1];
    int c2 = g_cand[n * 4 + 2], c3 = g_cand[n * 4 + 3];
    const float* e0 = emb + (size_t)c0 * EDIM;
    const float* e1 = emb + (size_t)c1 * EDIM;
    const float* e2p = emb + (size_t)c2 * EDIM;
    const float* e3 = emb + (size_t)c3 * EDIM;
    float d0 = 0.f, d1 = 0.f, d2 = 0.f, d3 = 0.f;
#pragma unroll 4
    for (int d = 0; d < EDIM; d++) {
        float x = lp[(size_t)d * PTS_PER_B];
        d0 = fmaf(x, e0[d], d0);
        d1 = fmaf(x, e1[d], d1);
        d2 = fmaf(x, e2p[d], d2);
        d3 = fmaf(x, e3[d], d3);
    }
    float x2 = g_x2[n];
    float best = 3.4e38f; int bk = 0x7fffffff;
    float dd; int kk;
    dd = __fsub_rn(__fadd_rn(x2, g_e2[c0]), __fmul_rn(2.f, d0)); kk = c0;
    if (dd < best || (dd == best && kk < bk)) { best = dd; bk = kk; }
    dd = __fsub_rn(__fadd_rn(x2, g_e2[c1]), __fmul_rn(2.f, d1)); kk = c1;
    if (dd < best || (dd == best && kk < bk)) { best = dd; bk = kk; }
    dd = __fsub_rn(__fadd_rn(x2, g_e2[c2]), __fmul_rn(2.f, d2)); kk = c2;
    if (dd < best || (dd == best && kk < bk)) { best = dd; bk = kk; }
    dd = __fsub_rn(__fadd_rn(x2, g_e2[c3]), __fmul_rn(2.f, d3)); kk = c3;
    if (dd < best || (dd == best && kk < bk)) { best = dd; bk = kk; }
    if (full) out[QUANT_ELEMS + 1 + n] = (float)bk;

    // gather write of quant_st (== code row, column-major output)
#pragma unroll 4
    for (int c = 0; c < EDIM; c++)
        out[base + (size_t)c * PTS_PER_B] = g_eT[c * NEMB + bk];

    __shared__ double s[256];
    s[t] = (double)best;
    __syncthreads();
    for (int o = 128; o > 0; o >>= 1) { if (t < o) s[t] += s[t + o]; __syncthreads(); }
    if (t == 0) atomicAdd(&g_loss_sum, s[0]);
}

__global__ void k_fin(float* out) {
    float m = (float)(g_loss_sum * (1.0 / (double)QUANT_ELEMS));
    out[QUANT_ELEMS] = __fadd_rn(m, __fmul_rn(0.25f, m));
}

// ---------------------------------------------------------------- launch
extern "C" void kernel_launch(void* const* d_in, const int* in_sizes, int n_in,
                              void* d_out, int out_size) {
    const float* lat = (const float*)d_in[0];
    const float* emb = (const float*)d_in[1];
    float* out = (float*)d_out;
    int full = (out_size >= QUANT_ELEMS + 1 + NPTS) ? 1 : 0;

    cudaFuncSetAttribute(k_dist_tc, cudaFuncAttributeMaxDynamicSharedMemorySize, SMEM_P1);
    cudaFuncSetAttribute(k_convX2, cudaFuncAttributeMaxDynamicSharedMemorySize, CONV_SMEM);

    k_zero<<<1, 1>>>();                                   // 0
    k_prep<<<NEMB, 256>>>(emb);                           // 1
    k_convX2<<<NPTS / 64, 256, CONV_SMEM>>>(lat);         // 2
    k_dist_tc<<<NPTS / 128, 256, SMEM_P1>>>();            // 3  <- profile slot
    k_rerank_out<<<NPTS / 256, 256>>>(lat, emb, out, full); // 4
    if (full) k_fin<<<1, 1>>>(out);                       // 5
}

// round 10
// speedup vs baseline: 1.9486x; 1.1165x over previous
#include <cuda_runtime.h>
#include <cuda_bf16.h>
#include <cstdint>

// ---------------------------------------------------------------- constants
#define NPTS      65536
#define EDIM      256
#define NEMB      1024
#define PTS_PER_B 1024
#define LAT_B_STRIDE 262144
#define QUANT_ELEMS 16777216

// ---------------------------------------------------------------- scratch
__device__ __nv_bfloat16 g_X[NPTS * EDIM];     // bf16(lat) transposed to [n][d]
__device__ __nv_bfloat16 g_E[NEMB * EDIM];     // bf16(embedding) [k][d]
__device__ float  g_eT[EDIM * NEMB];
__device__ float  g_e2[NEMB];
__device__ float  g_x2[NPTS];
__device__ int    g_cand[NPTS * 4];
__device__ double g_loss_sum;

// ---------------------------------------------------------------- helpers
__device__ __forceinline__ uint32_t smem_u32(const void* p) {
    uint32_t a;
    asm("{ .reg .u64 t; cvta.to.shared.u64 t, %1; cvt.u32.u64 %0, t; }" : "=r"(a) : "l"(p));
    return a;
}
__device__ __forceinline__ void cpasync16(uint32_t dst, const void* src) {
    asm volatile("cp.async.cg.shared.global [%0], [%1], 16;" :: "r"(dst), "l"(src));
}
#define CP_COMMIT() asm volatile("cp.async.commit_group;" ::: "memory")
#define CP_WAIT(n)  asm volatile("cp.async.wait_group %0;" :: "n"(n) : "memory")

__device__ __forceinline__ void ldm_x4(uint32_t& r0, uint32_t& r1, uint32_t& r2, uint32_t& r3,
                                       uint32_t addr) {
    asm volatile("ldmatrix.sync.aligned.m8n8.x4.shared.b16 {%0,%1,%2,%3}, [%4];"
        : "=r"(r0), "=r"(r1), "=r"(r2), "=r"(r3) : "r"(addr));
}
__device__ __forceinline__ void mma_bf16(float& c0, float& c1, float& c2, float& c3,
                                         uint32_t a0, uint32_t a1, uint32_t a2, uint32_t a3,
                                         uint32_t b0, uint32_t b1) {
    asm volatile("mma.sync.aligned.m16n8k16.row.col.f32.bf16.bf16.f32 "
        "{%0,%1,%2,%3}, {%4,%5,%6,%7}, {%8,%9}, {%0,%1,%2,%3};"
        : "+f"(c0), "+f"(c1), "+f"(c2), "+f"(c3)
        : "r"(a0), "r"(a1), "r"(a2), "r"(a3), "r"(b0), "r"(b1));
}

// ---------------------------------------------------------------- small kernels
__global__ void k_zero() { g_loss_sum = 0.0; }

__global__ __launch_bounds__(256) void k_prep(const float* __restrict__ emb) {
    int k = blockIdx.x, c = threadIdx.x;
    float v = emb[k * EDIM + c];
    g_eT[c * NEMB + k] = v;
    g_E[k * EDIM + c] = __float2bfloat16(v);
    __shared__ float s[256];
    s[c] = v * v;
    __syncthreads();
    for (int o = 128; o > 0; o >>= 1) { if (c < o) s[c] += s[c + o]; __syncthreads(); }
    if (c == 0) g_e2[k] = s[0];
}

// ---------------------------------------------------------------- fused transpose+bf16-convert+x2
#define CPAD 66
#define CONV_SMEM (256 * CPAD * 4)

__global__ __launch_bounds__(256, 3) void k_convX2(const float* __restrict__ lat) {
    extern __shared__ float sF[];
    int n0 = blockIdx.x * 64;
    int b = n0 >> 10, p0 = n0 & 1023;
    int t = threadIdx.x;
    int w = t >> 5, l = t & 31;
    const float* base = lat + (size_t)b * LAT_B_STRIDE + p0;

    int half = l >> 4;
    int pf = l & 15;
#pragma unroll
    for (int r = 0; r < 16; r++) {
        int d = w * 32 + r * 2 + half;
        float4 v = *(const float4*)(base + (size_t)d * PTS_PER_B + pf * 4);
        float* dst = sF + d * CPAD + pf * 4;
        dst[0] = v.x; dst[1] = v.y; dst[2] = v.z; dst[3] = v.w;
    }
    __syncthreads();

    int p = t >> 2, seg = t & 3;
    float s = 0.f;
    uint32_t pk[32];
#pragma unroll
    for (int j = 0; j < 32; j++) {
        float a = sF[(seg * 64 + 2 * j) * CPAD + p];
        float c = sF[(seg * 64 + 2 * j + 1) * CPAD + p];
        s = fmaf(a, a, s);
        s = fmaf(c, c, s);
        unsigned short lo = __bfloat16_as_ushort(__float2bfloat16(a));
        unsigned short hi = __bfloat16_as_ushort(__float2bfloat16(c));
        pk[j] = (uint32_t)lo | ((uint32_t)hi << 16);
    }
    uint4* dst = (uint4*)(g_X + (size_t)(n0 + p) * EDIM + seg * 64);
#pragma unroll
    for (int j = 0; j < 8; j++)
        dst[j] = make_uint4(pk[j * 4], pk[j * 4 + 1], pk[j * 4 + 2], pk[j * 4 + 3]);
    s += __shfl_xor_sync(0xffffffffu, s, 1);
    s += __shfl_xor_sync(0xffffffffu, s, 2);
    if (seg == 0) g_x2[n0 + p] = s;
}

// ---------------------------------------------------------------- bf16 HMMA distance + top-4
// 2 CTAs/SM: X tile resident (67584B) + 2 x 32-row E chunk buffers (2x16896B) + e2 (2x128B)
#define PADH 264
#define ROWB 528
#define XSZ  67584                 // 128 * 528
#define ECH  16896                 // 32 * 528
#define SM_ES   XSZ
#define SM_E2   (SM_ES + 2 * ECH)  // 101376
#define SMEM_P1 (SM_E2 + 256)     // 101632

__global__ __launch_bounds__(256, 2) void k_dist_tc() {
    extern __shared__ char smem[];
    uint32_t sb = smem_u32(smem);
    int tid = threadIdx.x;
    int wid = tid >> 5, l = tid & 31;   // warp = m-slice of 16 rows
    int gid = l >> 2, tig = l & 3;
    int n_base = blockIdx.x * 128;

    // ---- group 0: X tile (128x256 bf16) + E chunk0 + e2 chunk0
    for (int i = tid; i < 4224; i += 256) {
        int row = i / 33, v = i % 33;
        if (v < 32)
            cpasync16(sb + row * ROWB + v * 16, g_X + (size_t)(n_base + row) * EDIM + v * 8);
    }
    for (int i = tid; i < 1056; i += 256) {
        int row = i / 33, v = i % 33;
        if (v < 32)
            cpasync16(sb + SM_ES + row * ROWB + v * 16, g_E + (size_t)row * EDIM + v * 8);
    }
    if (tid < 8) cpasync16(sb + SM_E2 + tid * 16, g_e2 + tid * 4);
    CP_COMMIT();
    // ---- group 1: E chunk1
    for (int i = tid; i < 1056; i += 256) {
        int row = i / 33, v = i % 33;
        if (v < 32)
            cpasync16(sb + SM_ES + ECH + row * ROWB + v * 16, g_E + (size_t)(32 + row) * EDIM + v * 8);
    }
    if (tid < 8) cpasync16(sb + SM_E2 + 128 + tid * 16, g_e2 + 32 + tid * 4);
    CP_COMMIT();

    uint32_t a_off = (uint32_t)((wid * 16 + (l & 15)) * ROWB + ((l >> 4) & 1) * 16);
    uint32_t b_off[2];
#pragma unroll
    for (int jj = 0; jj < 2; jj++)
        b_off[jj] = (uint32_t)((jj * 16 + ((l >> 4) & 1) * 8 + (l & 7)) * ROWB
                               + ((l >> 3) & 1) * 16);

    float bd[2][4]; int bi[2][4];
#pragma unroll
    for (int s = 0; s < 2; s++)
#pragma unroll
        for (int q = 0; q < 4; q++) { bd[s][q] = 3.4e38f; bi[s][q] = 0; }

    for (int c = 0; c < 32; c++) {
        int buf = c & 1;
        if (c < 31) { CP_WAIT(1); } else { CP_WAIT(0); }
        __syncthreads();

        float acc[4][4];
#pragma unroll
        for (int jt = 0; jt < 4; jt++)
#pragma unroll
            for (int q = 0; q < 4; q++) acc[jt][q] = 0.f;

        uint32_t eb = sb + SM_ES + buf * ECH;
#pragma unroll 4
        for (int kc = 0; kc < 16; kc++) {
            uint32_t a[4], br[2][4];
            ldm_x4(a[0], a[1], a[2], a[3], sb + a_off + kc * 32);
#pragma unroll
            for (int jj = 0; jj < 2; jj++)
                ldm_x4(br[jj][0], br[jj][1], br[jj][2], br[jj][3], eb + b_off[jj] + kc * 32);
#pragma unroll
            for (int jt = 0; jt < 4; jt++)
                mma_bf16(acc[jt][0], acc[jt][1], acc[jt][2], acc[jt][3],
                         a[0], a[1], a[2], a[3],
                         br[jt >> 1][(jt & 1) * 2], br[jt >> 1][(jt & 1) * 2 + 1]);
        }

        // epilogue: rank by e2 - 2*dot (x2 per-point constant)
        int nck = c * 32;
        const float2* e2p = (const float2*)(smem + SM_E2 + buf * 128);
#pragma unroll
        for (int jt = 0; jt < 4; jt++) {
            float2 e2v = e2p[jt * 4 + tig];
            int nb0 = nck + jt * 8 + tig * 2;
#pragma unroll
            for (int s = 0; s < 2; s++) {
                float d0 = fmaf(-2.f, acc[jt][s * 2 + 0], e2v.x);
                float d1 = fmaf(-2.f, acc[jt][s * 2 + 1], e2v.y);
                if (d0 < bd[s][3]) {
                    float dv = d0; int iv = nb0;
#pragma unroll
                    for (int q = 0; q < 4; q++)
                        if (dv < bd[s][q]) {
                            float tf = bd[s][q]; int ti = bi[s][q];
                            bd[s][q] = dv; bi[s][q] = iv; dv = tf; iv = ti;
                        }
                }
                if (d1 < bd[s][3]) {
                    float dv = d1; int iv = nb0 + 1;
#pragma unroll
                    for (int q = 0; q < 4; q++)
                        if (dv < bd[s][q]) {
                            float tf = bd[s][q]; int ti = bi[s][q];
                            bd[s][q] = dv; bi[s][q] = iv; dv = tf; iv = ti;
                        }
                }
            }
        }
        __syncthreads();                       // all reads of buf done
        if (c + 2 < 32) {                      // prefetch chunk c+2 into buf
            int nc = c + 2;
            for (int i = tid; i < 1056; i += 256) {
                int row = i / 33, v = i % 33;
                if (v < 32)
                    cpasync16(sb + SM_ES + buf * ECH + row * ROWB + v * 16,
                              g_E + (size_t)(nc * 32 + row) * EDIM + v * 8);
            }
            if (tid < 8) cpasync16(sb + SM_E2 + buf * 128 + tid * 16, g_e2 + nc * 32 + tid * 4);
            CP_COMMIT();
        }
    }

    // ---- merge per-row top-4 across the 4 tig threads (reuse E smem)
    __syncthreads();
    float* sd = (float*)(smem + SM_ES);
    int*   si = (int*)(smem + SM_ES + 8192);
#pragma unroll
    for (int s = 0; s < 2; s++) {
        int row = wid * 16 + s * 8 + gid;
#pragma unroll
        for (int q = 0; q < 4; q++) {
            sd[row * 16 + tig * 4 + q] = bd[s][q];
            si[row * 16 + tig * 4 + q] = bi[s][q];
        }
    }
    __syncthreads();
    if (tid < 128) {
        float fb[4]; int fi[4];
#pragma unroll
        for (int q = 0; q < 4; q++) { fb[q] = 3.4e38f; fi[q] = 0; }
        for (int e = 0; e < 16; e++) {
            float dv = sd[tid * 16 + e]; int iv = si[tid * 16 + e];
            if (dv < fb[3]) {
#pragma unroll
                for (int q = 0; q < 4; q++)
                    if (dv < fb[q]) {
                        float tf = fb[q]; int ti = fi[q];
                        fb[q] = dv; fi[q] = iv; dv = tf; iv = ti;
                    }
            }
        }
#pragma unroll
        for (int q = 0; q < 4; q++) g_cand[(n_base + tid) * 4 + q] = fi[q];
    }
}

// ---------------------------------------------------------------- fused exact re-rank + loss + gather-write
__global__ __launch_bounds__(256) void k_rerank_out(const float* __restrict__ lat,
                                                    const float* __restrict__ emb,
                                                    float* __restrict__ out, int full) {
    int t = threadIdx.x;
    int n = blockIdx.x * 256 + t;
    int b = n >> 10, p = n & 1023;
    size_t base = (size_t)b * LAT_B_STRIDE + p;
    const float* lp = lat + base;
    int c0 = g_cand[n * 4 + 0], c1 = g_cand[n * 4 + 1];
    int c2 = g_cand[n * 4 + 2], c3 = g_cand[n * 4 + 3];
    const float* e0 = emb + (size_t)c0 * EDIM;
    const float* e1 = emb + (size_t)c1 * EDIM;
    const float* e2p = emb + (size_t)c2 * EDIM;
    const float* e3 = emb + (size_t)c3 * EDIM;
    float d0 = 0.f, d1 = 0.f, d2 = 0.f, d3 = 0.f;
#pragma unroll 4
    for (int d = 0; d < EDIM; d++) {
        float x = lp[(size_t)d * PTS_PER_B];
        d0 = fmaf(x, e0[d], d0);
        d1 = fmaf(x, e1[d], d1);
        d2 = fmaf(x, e2p[d], d2);
        d3 = fmaf(x, e3[d], d3);
    }
    float x2 = g_x2[n];
    float best = 3.4e38f; int bk = 0x7fffffff;
    float dd; int kk;
    dd = __fsub_rn(__fadd_rn(x2, g_e2[c0]), __fmul_rn(2.f, d0)); kk = c0;
    if (dd < best || (dd == best && kk < bk)) { best = dd; bk = kk; }
    dd = __fsub_rn(__fadd_rn(x2, g_e2[c1]), __fmul_rn(2.f, d1)); kk = c1;
    if (dd < best || (dd == best && kk < bk)) { best = dd; bk = kk; }
    dd = __fsub_rn(__fadd_rn(x2, g_e2[c2]), __fmul_rn(2.f, d2)); kk = c2;
    if (dd < best || (dd == best && kk < bk)) { best = dd; bk = kk; }
    dd = __fsub_rn(__fadd_rn(x2, g_e2[c3]), __fmul_rn(2.f, d3)); kk = c3;
    if (dd < best || (dd == best && kk < bk)) { best = dd; bk = kk; }
    if (full) out[QUANT_ELEMS + 1 + n] = (float)bk;

#pragma unroll 4
    for (int c = 0; c < EDIM; c++)
        out[base + (size_t)c * PTS_PER_B] = g_eT[c * NEMB + bk];

    __shared__ double s[256];
    s[t] = (double)best;
    __syncthreads();
    for (int o = 128; o > 0; o >>= 1) { if (t < o) s[t] += s[t + o]; __syncthreads(); }
    if (t == 0) atomicAdd(&g_loss_sum, s[0]);
}

__global__ void k_fin(float* out) {
    float m = (float)(g_loss_sum * (1.0 / (double)QUANT_ELEMS));
    out[QUANT_ELEMS] = __fadd_rn(m, __fmul_rn(0.25f, m));
}

// ---------------------------------------------------------------- launch
extern "C" void kernel_launch(void* const* d_in, const int* in_sizes, int n_in,
                              void* d_out, int out_size) {
    const float* lat = (const float*)d_in[0];
    const float* emb = (const float*)d_in[1];
    float* out = (float*)d_out;
    int full = (out_size >= QUANT_ELEMS + 1 + NPTS) ? 1 : 0;

    cudaFuncSetAttribute(k_dist_tc, cudaFuncAttributeMaxDynamicSharedMemorySize, SMEM_P1);
    cudaFuncSetAttribute(k_convX2, cudaFuncAttributeMaxDynamicSharedMemorySize, CONV_SMEM);

    k_zero<<<1, 1>>>();                                     // 0
    k_prep<<<NEMB, 256>>>(emb);                             // 1
    k_convX2<<<NPTS / 64, 256, CONV_SMEM>>>(lat);           // 2
    k_dist_tc<<<NPTS / 128, 256, SMEM_P1>>>();              // 3  <- profile slot
    k_rerank_out<<<NPTS / 256, 256>>>(lat, emb, out, full); // 4
    if (full) k_fin<<<1, 1>>>(out);                         // 5
}